// round 2
// baseline (speedup 1.0000x reference)
#include <cuda_runtime.h>
#include <math.h>

#define NN 131072
#define CC 128
#define SS 6
#define BB 6
#define EE 131072
#define ELL 32768
#define NLIST 12
#define GSEG 128            // NN / 1024 scan segments
#define OSTR (NN+4)         // padded offset stride (16B-aligned int4 access)
#define SMEM_BYTES (2*128*128*4)   // 128 KB dynamic smem for GEMM

// ---------------- device scratch (statically declared: no allocations) ----------------
__device__ float g_feat [(size_t)NN*CC];
__device__ float g_feat2[(size_t)NN*CC];
__device__ float g_temp [(size_t)NN*CC];
__device__ float g_agg  [(size_t)NLIST*NN*CC];   // 12 per-scale aggregates
__device__ float g_gath [(size_t)ELL*CC];
__device__ float g_gout [(size_t)ELL*CC];
__device__ int   g_cnt  [NLIST*NN];
__device__ int   g_offs [NLIST*OSTR];
__device__ int   g_cur  [NLIST*NN];
__device__ int   g_csrv [NLIST*EE];
__device__ int   g_part [NLIST*GSEG];

// ---------------- CSR build ----------------
__global__ void k_count(const int* __restrict__ pre_u, const int* __restrict__ suc_u) {
    int idx = blockIdx.x*256 + threadIdx.x;              // covers NLIST*EE
    int l = idx / EE, e = idx % EE;
    const int* u = (l < SS) ? (pre_u + (size_t)l*EE) : (suc_u + (size_t)(l-SS)*EE);
    atomicAdd(&g_cnt[l*NN + u[e]], 1);
}

__global__ void k_scanA() {
    int l = blockIdx.y, seg = blockIdx.x, t = threadIdx.x;
    int base = seg*1024 + t*4;
    int4 c = *(const int4*)&g_cnt[l*NN + base];
    int s4 = c.x + c.y + c.z + c.w;
    int lane = t & 31, w = t >> 5;
    int inc = s4;
    #pragma unroll
    for (int o = 1; o < 32; o <<= 1) { int q = __shfl_up_sync(0xffffffffu, inc, o); if (lane >= o) inc += q; }
    __shared__ int wsum[8];
    if (lane == 31) wsum[w] = inc;
    __syncthreads();
    if (w == 0) {
        int v = (lane < 8) ? wsum[lane] : 0;
        #pragma unroll
        for (int o = 1; o < 8; o <<= 1) { int q = __shfl_up_sync(0xffffffffu, v, o); if (lane >= o) v += q; }
        if (lane < 8) wsum[lane] = v;     // inclusive warp prefix
    }
    __syncthreads();
    int excl = inc - s4 + (w > 0 ? wsum[w-1] : 0);
    int ob = l*OSTR + base;
    g_offs[ob+0] = excl;
    g_offs[ob+1] = excl + c.x;
    g_offs[ob+2] = excl + c.x + c.y;
    g_offs[ob+3] = excl + c.x + c.y + c.z;
    if (t == 255) g_part[l*GSEG + seg] = excl + s4;      // segment total
}

__global__ void k_scanB() {
    int l = blockIdx.x, t = threadIdx.x, lane = t & 31, w = t >> 5;
    int v = g_part[l*GSEG + t];
    int inc = v;
    #pragma unroll
    for (int o = 1; o < 32; o <<= 1) { int q = __shfl_up_sync(0xffffffffu, inc, o); if (lane >= o) inc += q; }
    __shared__ int ws[4];
    if (lane == 31) ws[w] = inc;
    __syncthreads();
    int add = 0;
    #pragma unroll
    for (int j = 0; j < 4; j++) if (j < w) add += ws[j];
    g_part[l*GSEG + t] = inc - v + add;                  // exclusive
}

__global__ void k_scanC() {
    int l = blockIdx.y, seg = blockIdx.x, t = threadIdx.x;
    int add = g_part[l*GSEG + seg];
    int base = seg*1024 + t*4;
    int ob = l*OSTR + base;
    int4 o = *(const int4*)&g_offs[ob];
    o.x += add; o.y += add; o.z += add; o.w += add;
    *(int4*)&g_offs[ob] = o;
    *(int4*)&g_cur[l*NN + base] = o;
    if (seg == 0 && t == 0) g_offs[l*OSTR + NN] = EE;
}

__global__ void k_fill(const int* __restrict__ pre_u, const int* __restrict__ pre_v,
                       const int* __restrict__ suc_u, const int* __restrict__ suc_v) {
    int idx = blockIdx.x*256 + threadIdx.x;
    int l = idx / EE, e = idx % EE;
    const int *u, *v;
    if (l < SS) { u = pre_u + (size_t)l*EE;      v = pre_v + (size_t)l*EE; }
    else        { u = suc_u + (size_t)(l-SS)*EE; v = suc_v + (size_t)(l-SS)*EE; }
    int p = atomicAdd(&g_cur[l*NN + u[e]], 1);
    g_csrv[l*EE + p] = v[e];
}

// ---------------- per-scale neighbor aggregation (pull via CSR; no atomics) ----------------
__global__ void k_aggregate() {
    int l = blockIdx.y;
    int warp = threadIdx.x >> 5, lane = threadIdx.x & 31;
    int n = blockIdx.x*8 + warp;
    int s = g_offs[l*OSTR + n], e2 = g_offs[l*OSTR + n + 1];
    float4 acc = make_float4(0.f, 0.f, 0.f, 0.f);
    for (int j = s; j < e2; j++) {
        int v = g_csrv[l*EE + j];
        float4 f = *(const float4*)&g_feat[(size_t)v*CC + lane*4];
        acc.x += f.x; acc.y += f.y; acc.z += f.z; acc.w += f.w;
    }
    *(float4*)&g_agg[(size_t)l*NN*CC + (size_t)n*CC + lane*4] = acc;
}

// ---------------- multi-chunk SGEMM: out[M,128] = sum_ch A_ch[M,128] @ W_ch[128,128] ----------------
// epilogue modes: 0 = plain store; 1 = GroupNorm(g,b); 3 = GroupNorm + residual + relu
struct GemmP {
    const float* A[13];
    const float* W[13];
    int nch;
    int mode;
    const float* g; const float* b; const float* res;
    float* out;
};

__global__ __launch_bounds__(256, 1) void k_gemm(GemmP p) {
    extern __shared__ float sm[];
    float* As = sm;              // [128][128] row-major [m][k]
    float* Bs = sm + 16384;      // [128][128] [k][n]
    float* Cs = sm;              // overlay, stride 132
    int tid = threadIdx.x;
    int m0 = blockIdx.x * 128;
    int tm = (tid >> 4) << 3;    // 0..120 step 8
    int tn = (tid & 15) << 3;

    float acc[8][8];
    #pragma unroll
    for (int i = 0; i < 8; i++)
        #pragma unroll
        for (int j = 0; j < 8; j++) acc[i][j] = 0.f;

    for (int ch = 0; ch < p.nch; ch++) {
        const float* Ag = p.A[ch] + (size_t)m0*CC;
        const float* Wg = p.W[ch];
        __syncthreads();
        #pragma unroll
        for (int r = 0; r < 16; r++) {
            int m  = (r << 3) + (tid >> 5);
            int kq = (tid & 31) << 2;
            *(float4*)&As[m*CC + kq] = *(const float4*)&Ag[(size_t)m*CC + kq];
            *(float4*)&Bs[m*CC + kq] = *(const float4*)&Wg[(size_t)m*CC + kq];
        }
        __syncthreads();
        #pragma unroll 4
        for (int k = 0; k < CC; k++) {
            float a[8];
            #pragma unroll
            for (int i = 0; i < 8; i++) a[i] = As[(tm+i)*CC + k];
            float4 b0 = *(const float4*)&Bs[k*CC + tn];
            float4 b1 = *(const float4*)&Bs[k*CC + tn + 4];
            float bb[8] = {b0.x, b0.y, b0.z, b0.w, b1.x, b1.y, b1.z, b1.w};
            #pragma unroll
            for (int i = 0; i < 8; i++)
                #pragma unroll
                for (int j = 0; j < 8; j++)
                    acc[i][j] = fmaf(a[i], bb[j], acc[i][j]);
        }
    }

    // stage C tile for row-complete epilogue
    __syncthreads();
    #pragma unroll
    for (int i = 0; i < 8; i++) {
        *(float4*)&Cs[(tm+i)*132 + tn]     = make_float4(acc[i][0], acc[i][1], acc[i][2], acc[i][3]);
        *(float4*)&Cs[(tm+i)*132 + tn + 4] = make_float4(acc[i][4], acc[i][5], acc[i][6], acc[i][7]);
    }
    __syncthreads();

    int lane = tid & 31, w = tid >> 5;
    for (int r = w; r < 128; r += 8) {
        float4 v = *(const float4*)&Cs[r*132 + lane*4];
        size_t go = (size_t)(m0 + r)*CC + lane*4;
        if (p.mode == 0) { *(float4*)&p.out[go] = v; continue; }
        float s  = v.x + v.y + v.z + v.w;
        float sq = v.x*v.x + v.y*v.y + v.z*v.z + v.w*v.w;
        #pragma unroll
        for (int o = 16; o > 0; o >>= 1) {
            s  += __shfl_xor_sync(0xffffffffu, s,  o);
            sq += __shfl_xor_sync(0xffffffffu, sq, o);
        }
        float mu  = s  * (1.0f/CC);
        float var = sq * (1.0f/CC) - mu*mu;
        float sc  = rsqrtf(var + 1e-5f);
        float4 gg = *(const float4*)&p.g[lane*4];
        float4 bv = *(const float4*)&p.b[lane*4];
        float4 y;
        y.x = (v.x - mu)*sc*gg.x + bv.x;
        y.y = (v.y - mu)*sc*gg.y + bv.y;
        y.z = (v.z - mu)*sc*gg.z + bv.z;
        y.w = (v.w - mu)*sc*gg.w + bv.w;
        if (p.mode == 3) {
            float4 rr = *(const float4*)&p.res[go];
            y.x += rr.x; y.y += rr.y; y.z += rr.z; y.w += rr.w;
            y.x = fmaxf(y.x, 0.f); y.y = fmaxf(y.y, 0.f);
            y.z = fmaxf(y.z, 0.f); y.w = fmaxf(y.w, 0.f);
        }
        *(float4*)&p.out[go] = y;
    }
}

// ---------------- small elementwise / row kernels ----------------
__global__ void k_mlp(const float* __restrict__ x, const float* __restrict__ w0,
                      const float* __restrict__ b0, float* __restrict__ out) {
    int idx = blockIdx.x*256 + threadIdx.x;   // NN*32
    int n = idx >> 5, q = (idx & 31) << 2;
    float x0 = x[(size_t)n*2], x1 = x[(size_t)n*2 + 1];
    float4 wa = *(const float4*)&w0[q];
    float4 wb = *(const float4*)&w0[CC + q];
    float4 bb = *(const float4*)&b0[q];
    float4 h;
    h.x = fmaxf(fmaf(x1, wb.x, fmaf(x0, wa.x, bb.x)), 0.f);
    h.y = fmaxf(fmaf(x1, wb.y, fmaf(x0, wa.y, bb.y)), 0.f);
    h.z = fmaxf(fmaf(x1, wb.z, fmaf(x0, wa.z, bb.z)), 0.f);
    h.w = fmaxf(fmaf(x1, wb.w, fmaf(x0, wa.w, bb.w)), 0.f);
    *(float4*)&out[(size_t)n*CC + q] = h;
}

__global__ void k_addrelu(const float* __restrict__ a, const float* __restrict__ b) {
    size_t idx = (size_t)(blockIdx.x*256 + threadIdx.x) * 4;
    float4 u = *(const float4*)&a[idx];
    float4 v = *(const float4*)&b[idx];
    float4 y;
    y.x = fmaxf(u.x + v.x, 0.f); y.y = fmaxf(u.y + v.y, 0.f);
    y.z = fmaxf(u.z + v.z, 0.f); y.w = fmaxf(u.w + v.w, 0.f);
    *(float4*)&g_feat[idx] = y;
}

__global__ void k_gn_relu(const float* __restrict__ g, const float* __restrict__ b) {
    int row = blockIdx.x*8 + (threadIdx.x >> 5);
    int lane = threadIdx.x & 31;
    float4 v = *(const float4*)&g_temp[(size_t)row*CC + lane*4];
    float s  = v.x + v.y + v.z + v.w;
    float sq = v.x*v.x + v.y*v.y + v.z*v.z + v.w*v.w;
    #pragma unroll
    for (int o = 16; o > 0; o >>= 1) {
        s  += __shfl_xor_sync(0xffffffffu, s,  o);
        sq += __shfl_xor_sync(0xffffffffu, sq, o);
    }
    float mu  = s  * (1.0f/CC);
    float var = sq * (1.0f/CC) - mu*mu;
    float sc  = rsqrtf(var + 1e-5f);
    float4 gg = *(const float4*)&g[lane*4];
    float4 bv = *(const float4*)&b[lane*4];
    float4 y;
    y.x = fmaxf((v.x - mu)*sc*gg.x + bv.x, 0.f);
    y.y = fmaxf((v.y - mu)*sc*gg.y + bv.y, 0.f);
    y.z = fmaxf((v.z - mu)*sc*gg.z + bv.z, 0.f);
    y.w = fmaxf((v.w - mu)*sc*gg.w + bv.w, 0.f);
    *(float4*)&g_feat2[(size_t)row*CC + lane*4] = y;
}

__global__ void k_gather(const int* __restrict__ vl) {
    int idx = blockIdx.x*256 + threadIdx.x;   // ELL*32
    int e = idx >> 5, q = (idx & 31) << 2;
    int v = vl[e];
    *(float4*)&g_gath[(size_t)e*CC + q] = *(const float4*)&g_feat[(size_t)v*CC + q];
}

__global__ void k_scatter(const int* __restrict__ ul) {
    int idx = blockIdx.x*256 + threadIdx.x;
    int e = idx >> 5, q = (idx & 31) << 2;
    int u = ul[e];
    float4 f = *(const float4*)&g_gout[(size_t)e*CC + q];
    float* d = &g_temp[(size_t)u*CC + q];
    atomicAdd(d + 0, f.x); atomicAdd(d + 1, f.y);
    atomicAdd(d + 2, f.z); atomicAdd(d + 3, f.w);
}

// ---------------- host orchestration ----------------
extern "C" void kernel_launch(void* const* d_in, const int* in_sizes, int n_in,
                              void* d_out, int out_size) {
    const float* ctrs   = (const float*)d_in[0];
    const float* feats  = (const float*)d_in[1];
    const int* pre_u    = (const int*)d_in[2];
    const int* pre_v    = (const int*)d_in[3];
    const int* suc_u    = (const int*)d_in[4];
    const int* suc_v    = (const int*)d_in[5];
    const int* left_u   = (const int*)d_in[6];
    const int* left_v   = (const int*)d_in[7];
    const int* right_u  = (const int*)d_in[8];
    const int* right_v  = (const int*)d_in[9];
    const float* ic_w0  = (const float*)d_in[10];
    const float* ic_b0  = (const float*)d_in[11];
    const float* ic_w1  = (const float*)d_in[12];
    const float* ic_g   = (const float*)d_in[13];
    const float* ic_bt  = (const float*)d_in[14];
    const float* if_w0  = (const float*)d_in[15];
    const float* if_b0  = (const float*)d_in[16];
    const float* if_w1  = (const float*)d_in[17];
    const float* if_g   = (const float*)d_in[18];
    const float* if_bt  = (const float*)d_in[19];
    const float* ctr_w  = (const float*)d_in[20];
    const float* pre_w  = (const float*)d_in[21];
    const float* suc_w  = (const float*)d_in[22];
    const float* left_w = (const float*)d_in[23];
    const float* right_w= (const float*)d_in[24];
    const float* norm_g = (const float*)d_in[25];
    const float* norm_b = (const float*)d_in[26];
    const float* ctr2_w = (const float*)d_in[27];
    const float* ctr2_g = (const float*)d_in[28];
    const float* ctr2_b = (const float*)d_in[29];

    void* q;
    float *fp, *f2p, *tp, *ap, *gp, *gop; void* cntp;
    cudaGetSymbolAddress(&q, g_feat);  fp  = (float*)q;
    cudaGetSymbolAddress(&q, g_feat2); f2p = (float*)q;
    cudaGetSymbolAddress(&q, g_temp);  tp  = (float*)q;
    cudaGetSymbolAddress(&q, g_agg);   ap  = (float*)q;
    cudaGetSymbolAddress(&q, g_gath);  gp  = (float*)q;
    cudaGetSymbolAddress(&q, g_gout);  gop = (float*)q;
    cudaGetSymbolAddress(&cntp, g_cnt);

    cudaFuncSetAttribute(k_gemm, cudaFuncAttributeMaxDynamicSharedMemorySize, SMEM_BYTES);

    // ---- CSR build (index arrays are launch-constant; rebuilt every call for determinism rules) ----
    cudaMemsetAsync(cntp, 0, sizeof(int)*NLIST*NN, 0);
    k_count<<<NLIST*EE/256, 256>>>(pre_u, suc_u);
    k_scanA<<<dim3(GSEG, NLIST), 256>>>();
    k_scanB<<<NLIST, GSEG>>>();
    k_scanC<<<dim3(GSEG, NLIST), 256>>>();
    k_fill<<<NLIST*EE/256, 256>>>(pre_u, pre_v, suc_u, suc_v);

    // ---- input MLPs: h = relu(x @ w0 + b0); f = GN(h @ w1) ----
    k_mlp<<<NN*32/256, 256>>>(ctrs,  ic_w0, ic_b0, tp);
    k_mlp<<<NN*32/256, 256>>>(feats, if_w0, if_b0, f2p);
    {
        GemmP p = {};
        p.A[0] = tp; p.W[0] = ic_w1; p.nch = 1; p.mode = 1;
        p.g = ic_g; p.b = ic_bt; p.out = ap;
        k_gemm<<<NN/128, 256, SMEM_BYTES>>>(p);
        p.A[0] = f2p; p.W[0] = if_w1; p.g = if_g; p.b = if_bt;
        p.out = ap + (size_t)NN*CC;
        k_gemm<<<NN/128, 256, SMEM_BYTES>>>(p);
    }
    k_addrelu<<<NN*32/256, 256>>>(ap, ap + (size_t)NN*CC);   // -> g_feat

    // ---- 6 fusion blocks ----
    for (int i = 0; i < BB; i++) {
        k_aggregate<<<dim3(NN/8, NLIST), 256>>>();

        GemmP pb = {};
        pb.A[0] = fp; pb.W[0] = ctr_w + (size_t)i*CC*CC;
        for (int s = 0; s < SS; s++) {
            pb.A[1+s] = ap + (size_t)s*NN*CC;
            pb.W[1+s] = pre_w + (size_t)(i*SS + s)*CC*CC;
            pb.A[7+s] = ap + (size_t)(SS + s)*NN*CC;
            pb.W[7+s] = suc_w + (size_t)(i*SS + s)*CC*CC;
        }
        pb.nch = 13; pb.mode = 0; pb.out = tp;
        k_gemm<<<NN/128, 256, SMEM_BYTES>>>(pb);

        // left / right: gather -> small GEMM -> atomic scatter-add into temp
        {
            GemmP ps = {};
            ps.nch = 1; ps.mode = 0; ps.A[0] = gp; ps.out = gop;
            k_gather<<<ELL*32/256, 256>>>(left_v);
            ps.W[0] = left_w + (size_t)i*CC*CC;
            k_gemm<<<ELL/128, 256, SMEM_BYTES>>>(ps);
            k_scatter<<<ELL*32/256, 256>>>(left_u);
            k_gather<<<ELL*32/256, 256>>>(right_v);
            ps.W[0] = right_w + (size_t)i*CC*CC;
            k_gemm<<<ELL/128, 256, SMEM_BYTES>>>(ps);
            k_scatter<<<ELL*32/256, 256>>>(right_u);
        }

        // feat2 = relu(GN(temp))
        k_gn_relu<<<NN/8, 256>>>(norm_g + (size_t)i*CC, norm_b + (size_t)i*CC);

        // feat = relu(GN(feat2 @ ctr2_w) + identity)   (identity == current g_feat)
        {
            GemmP p2 = {};
            p2.A[0] = f2p; p2.W[0] = ctr2_w + (size_t)i*CC*CC;
            p2.nch = 1; p2.mode = 3;
            p2.g = ctr2_g + (size_t)i*CC; p2.b = ctr2_b + (size_t)i*CC;
            p2.res = fp;
            p2.out = (i == BB-1) ? (float*)d_out : fp;
            k_gemm<<<NN/128, 256, SMEM_BYTES>>>(p2);
        }
    }
}

// round 5
// speedup vs baseline: 2.3588x; 2.3588x over previous
#include <cuda_runtime.h>
#include <cuda_bf16.h>
#include <math.h>
#include <stdint.h>

#define NN 131072
#define CC 128
#define SS 6
#define BB 6
#define EE 131072
#define ELL 32768
#define NLIST 12
#define GSEG 128
#define OSTR (NN+4)
#define NSLOT 98
#define WSTR 20                      // staged row stride in b32 words (16 used + 4 pad -> conflict-free)
#define SMEM_TC 67584                // Cs 128*132*4 (stage buffers overlay: 4*128*20*4 = 40960)

// ---------------- device scratch ----------------
__device__ float g_feat [(size_t)NN*CC];
__device__ float g_feat2[(size_t)NN*CC];
__device__ float g_temp [(size_t)NN*CC];
__device__ float g_agg  [(size_t)NLIST*NN*CC];
__device__ float g_gath [(size_t)ELL*CC];
__device__ float g_gout [(size_t)ELL*CC];
__device__ unsigned short g_wth[(size_t)NSLOT*16384];  // transposed bf16-hi weights [slot][n][k]
__device__ unsigned short g_wtl[(size_t)NSLOT*16384];  // transposed bf16-lo weights
__device__ int   g_cnt  [NLIST*NN];
__device__ int   g_offs [NLIST*OSTR];
__device__ int   g_cur  [NLIST*NN];
__device__ int   g_csrv [NLIST*EE];
__device__ int   g_part [NLIST*GSEG];

// ---------------- helpers ----------------
__device__ __forceinline__ uint32_t pack_bf16x2(float lo, float hi) {
    __nv_bfloat162 h2 = __floats2bfloat162_rn(lo, hi);   // .x = lo, .y = hi
    return *reinterpret_cast<uint32_t*>(&h2);
}
__device__ __forceinline__ float bf16_hi_f(float a) {
    return __bfloat162float(__float2bfloat16_rn(a));
}
__device__ __forceinline__ void mma_bf16(float* d, const uint32_t* a, uint32_t b0, uint32_t b1) {
    asm volatile(
        "mma.sync.aligned.m16n8k16.row.col.f32.bf16.bf16.f32 "
        "{%0,%1,%2,%3}, {%4,%5,%6,%7}, {%8,%9}, {%0,%1,%2,%3};"
        : "+f"(d[0]), "+f"(d[1]), "+f"(d[2]), "+f"(d[3])
        : "r"(a[0]), "r"(a[1]), "r"(a[2]), "r"(a[3]), "r"(b0), "r"(b1));
}

// ---------------- CSR build ----------------
__global__ void k_count(const int* __restrict__ pre_u, const int* __restrict__ suc_u) {
    int idx = blockIdx.x*256 + threadIdx.x;
    int l = idx / EE, e = idx % EE;
    const int* u = (l < SS) ? (pre_u + (size_t)l*EE) : (suc_u + (size_t)(l-SS)*EE);
    atomicAdd(&g_cnt[l*NN + u[e]], 1);
}

__global__ void k_scanA() {
    int l = blockIdx.y, seg = blockIdx.x, t = threadIdx.x;
    int base = seg*1024 + t*4;
    int4 c = *(const int4*)&g_cnt[l*NN + base];
    int s4 = c.x + c.y + c.z + c.w;
    int lane = t & 31, w = t >> 5;
    int inc = s4;
    #pragma unroll
    for (int o = 1; o < 32; o <<= 1) { int q = __shfl_up_sync(0xffffffffu, inc, o); if (lane >= o) inc += q; }
    __shared__ int wsum[8];
    if (lane == 31) wsum[w] = inc;
    __syncthreads();
    if (w == 0) {
        int v = (lane < 8) ? wsum[lane] : 0;
        #pragma unroll
        for (int o = 1; o < 8; o <<= 1) { int q = __shfl_up_sync(0xffffffffu, v, o); if (lane >= o) v += q; }
        if (lane < 8) wsum[lane] = v;
    }
    __syncthreads();
    int excl = inc - s4 + (w > 0 ? wsum[w-1] : 0);
    int ob = l*OSTR + base;
    g_offs[ob+0] = excl;
    g_offs[ob+1] = excl + c.x;
    g_offs[ob+2] = excl + c.x + c.y;
    g_offs[ob+3] = excl + c.x + c.y + c.z;
    if (t == 255) g_part[l*GSEG + seg] = excl + s4;
}

__global__ void k_scanB() {
    int l = blockIdx.x, t = threadIdx.x, lane = t & 31, w = t >> 5;
    int v = g_part[l*GSEG + t];
    int inc = v;
    #pragma unroll
    for (int o = 1; o < 32; o <<= 1) { int q = __shfl_up_sync(0xffffffffu, inc, o); if (lane >= o) inc += q; }
    __shared__ int ws[4];
    if (lane == 31) ws[w] = inc;
    __syncthreads();
    int add = 0;
    #pragma unroll
    for (int j = 0; j < 4; j++) if (j < w) add += ws[j];
    g_part[l*GSEG + t] = inc - v + add;
}

__global__ void k_scanC() {
    int l = blockIdx.y, seg = blockIdx.x, t = threadIdx.x;
    int add = g_part[l*GSEG + seg];
    int base = seg*1024 + t*4;
    int ob = l*OSTR + base;
    int4 o = *(const int4*)&g_offs[ob];
    o.x += add; o.y += add; o.z += add; o.w += add;
    *(int4*)&g_offs[ob] = o;
    *(int4*)&g_cur[l*NN + base] = o;
    if (seg == 0 && t == 0) g_offs[l*OSTR + NN] = EE;
}

__global__ void k_fill(const int* __restrict__ pre_u, const int* __restrict__ pre_v,
                       const int* __restrict__ suc_u, const int* __restrict__ suc_v) {
    int idx = blockIdx.x*256 + threadIdx.x;
    int l = idx / EE, e = idx % EE;
    const int *u, *v;
    if (l < SS) { u = pre_u + (size_t)l*EE;      v = pre_v + (size_t)l*EE; }
    else        { u = suc_u + (size_t)(l-SS)*EE; v = suc_v + (size_t)(l-SS)*EE; }
    int p = atomicAdd(&g_cur[l*NN + u[e]], 1);
    g_csrv[l*EE + p] = v[e];
}

// ---------------- aggregation (pull, CSR) ----------------
__global__ void k_aggregate() {
    int l = blockIdx.y;
    int warp = threadIdx.x >> 5, lane = threadIdx.x & 31;
    int n = blockIdx.x*8 + warp;
    int s = g_offs[l*OSTR + n], e2 = g_offs[l*OSTR + n + 1];
    float4 acc = make_float4(0.f, 0.f, 0.f, 0.f);
    for (int j = s; j < e2; j++) {
        int v = g_csrv[l*EE + j];
        float4 f = *(const float4*)&g_feat[(size_t)v*CC + lane*4];
        acc.x += f.x; acc.y += f.y; acc.z += f.z; acc.w += f.w;
    }
    *(float4*)&g_agg[(size_t)l*NN*CC + (size_t)n*CC + lane*4] = acc;
}

// ---------------- weight prep: transpose + bf16 hi/lo split ----------------
__global__ void k_wprep(const float* __restrict__ ic_w1, const float* __restrict__ if_w1,
                        const float* __restrict__ ctr_w, const float* __restrict__ pre_w,
                        const float* __restrict__ suc_w, const float* __restrict__ left_w,
                        const float* __restrict__ right_w, const float* __restrict__ ctr2_w) {
    int slot = blockIdx.x;
    const float* src;
    if (slot == 0) src = ic_w1;
    else if (slot == 1) src = if_w1;
    else {
        int s2 = slot - 2, i = s2 / 16, j = s2 % 16;
        if (j == 0)       src = ctr_w   + (size_t)i*16384;
        else if (j <= 6)  src = pre_w   + (size_t)(i*6 + j-1)*16384;
        else if (j <= 12) src = suc_w   + (size_t)(i*6 + j-7)*16384;
        else if (j == 13) src = left_w  + (size_t)i*16384;
        else if (j == 14) src = right_w + (size_t)i*16384;
        else              src = ctr2_w  + (size_t)i*16384;
    }
    unsigned short* dh = g_wth + (size_t)slot*16384;
    unsigned short* dl = g_wtl + (size_t)slot*16384;
    for (int idx = threadIdx.x; idx < 16384; idx += 256) {
        int n = idx >> 7, k = idx & 127;
        float w = src[(size_t)k*CC + n];            // W[k][n] -> Wt[n][k]
        __nv_bfloat16 h = __float2bfloat16_rn(w);
        float hf = __bfloat162float(h);
        __nv_bfloat16 l = __float2bfloat16_rn(w - hf);
        dh[idx] = *reinterpret_cast<unsigned short*>(&h);
        dl[idx] = *reinterpret_cast<unsigned short*>(&l);
    }
}

// ---------------- bf16 mma.sync multi-chunk GEMM + fused epilogue ----------------
// out[M,128] = sum_ch A_ch[M,128] @ W_ch[128,128]   (3-term bf16 split ~fp32 accuracy)
// mode: 0 = plain store; 1 = GroupNorm; 3 = GroupNorm + residual + relu
struct GemmP {
    const float* A[13];
    int slot[13];
    int nch;
    int mode;
    const float* g; const float* b; const float* res;
    float* out;
};

__global__ __launch_bounds__(256, 2) void k_gemm_tc(GemmP p) {
    extern __shared__ uint32_t sw[];
    // staged word arrays: [128 rows][WSTR words], words = packed bf16x2 (k even low, k odd high)
    uint32_t* Ah = sw;
    uint32_t* Al = sw + 128*WSTR;
    uint32_t* Bh = sw + 2*128*WSTR;
    uint32_t* Bl = sw + 3*128*WSTR;
    float* Cs = (float*)sw;          // epilogue overlay, stride 132

    int tid = threadIdx.x, wid = tid >> 5, lane = tid & 31;
    int g = lane >> 2, t4 = lane & 3;
    int wm = wid & 3, wn = wid >> 2;         // warp tile: rows wm*32, cols wn*64
    int m0 = blockIdx.x * 128;

    float acc[2][8][4];
    #pragma unroll
    for (int i = 0; i < 2; i++)
        #pragma unroll
        for (int j = 0; j < 8; j++)
            #pragma unroll
            for (int q = 0; q < 4; q++) acc[i][j][q] = 0.f;

    int lrow = tid >> 1, lkh = (tid & 1) << 4;     // loader: row 0..127, k-half 0/16

    for (int ch = 0; ch < p.nch; ch++) {
        const float* Ag = p.A[ch] + (size_t)m0*CC;
        const unsigned short* Wh = g_wth + (size_t)p.slot[ch]*16384;
        const unsigned short* Wl = g_wtl + (size_t)p.slot[ch]*16384;
        for (int st = 0; st < 4; st++) {
            int k0 = st*32 + lkh;
            // ---- stage A: fp32 -> bf16 hi/lo words ----
            {
                const float* src = Ag + (size_t)lrow*CC + k0;
                float f[16];
                #pragma unroll
                for (int i = 0; i < 4; i++) {
                    float4 v = *(const float4*)(src + i*4);
                    f[i*4+0] = v.x; f[i*4+1] = v.y; f[i*4+2] = v.z; f[i*4+3] = v.w;
                }
                uint32_t hw[8], lw[8];
                #pragma unroll
                for (int j = 0; j < 8; j++) {
                    float a0 = f[2*j], a1 = f[2*j+1];
                    float h0 = bf16_hi_f(a0), h1 = bf16_hi_f(a1);
                    hw[j] = pack_bf16x2(h0, h1);
                    lw[j] = pack_bf16x2(a0 - h0, a1 - h1);
                }
                uint32_t* da = Ah + lrow*WSTR + (lkh >> 1);
                *(uint4*)(da)     = make_uint4(hw[0], hw[1], hw[2], hw[3]);
                *(uint4*)(da + 4) = make_uint4(hw[4], hw[5], hw[6], hw[7]);
                uint32_t* dl = Al + lrow*WSTR + (lkh >> 1);
                *(uint4*)(dl)     = make_uint4(lw[0], lw[1], lw[2], lw[3]);
                *(uint4*)(dl + 4) = make_uint4(lw[4], lw[5], lw[6], lw[7]);
            }
            // ---- stage B: copy pre-split bf16 weights with relayout ----
            {
                const unsigned short* sh = Wh + (size_t)lrow*CC + k0;
                const unsigned short* sl = Wl + (size_t)lrow*CC + k0;
                uint4 vh0 = *(const uint4*)sh;          // 8 bf16 = 4 words (k0..k0+7)
                uint4 vh1 = *(const uint4*)(sh + 8);
                uint4 vl0 = *(const uint4*)sl;
                uint4 vl1 = *(const uint4*)(sl + 8);
                uint32_t* db = Bh + lrow*WSTR + (lkh >> 1);
                *(uint4*)(db)     = vh0;
                *(uint4*)(db + 4) = vh1;
                uint32_t* dbl = Bl + lrow*WSTR + (lkh >> 1);
                *(uint4*)(dbl)     = vl0;
                *(uint4*)(dbl + 4) = vl1;
            }
            __syncthreads();
            // ---- compute: 2 k16 groups ----
            #pragma unroll
            for (int kg = 0; kg < 2; kg++) {
                int kw = kg*8 + t4;
                uint32_t ah[2][4], al_[2][4];
                #pragma unroll
                for (int mf = 0; mf < 2; mf++) {
                    int r0 = (wm*32 + mf*16 + g) * WSTR;
                    int r1 = r0 + 8*WSTR;
                    ah[mf][0] = Ah[r0 + kw];     ah[mf][1] = Ah[r1 + kw];
                    ah[mf][2] = Ah[r0 + kw + 4]; ah[mf][3] = Ah[r1 + kw + 4];
                    al_[mf][0] = Al[r0 + kw];     al_[mf][1] = Al[r1 + kw];
                    al_[mf][2] = Al[r0 + kw + 4]; al_[mf][3] = Al[r1 + kw + 4];
                }
                #pragma unroll
                for (int nf = 0; nf < 8; nf++) {
                    int nb = (wn*64 + nf*8 + g) * WSTR;
                    uint32_t bh0 = Bh[nb + kw], bh1 = Bh[nb + kw + 4];
                    uint32_t bl0 = Bl[nb + kw], bl1 = Bl[nb + kw + 4];
                    #pragma unroll
                    for (int mf = 0; mf < 2; mf++) {
                        mma_bf16(acc[mf][nf], ah[mf], bh0, bh1);
                        mma_bf16(acc[mf][nf], ah[mf], bl0, bl1);
                        mma_bf16(acc[mf][nf], al_[mf], bh0, bh1);
                    }
                }
            }
            __syncthreads();
        }
    }

    // ---- stage C to smem for row-complete epilogue ----
    #pragma unroll
    for (int mf = 0; mf < 2; mf++) {
        #pragma unroll
        for (int nf = 0; nf < 8; nf++) {
            int r0 = wm*32 + mf*16 + g;
            int cb = wn*64 + nf*8 + t4*2;
            *(float2*)&Cs[r0*132 + cb]     = make_float2(acc[mf][nf][0], acc[mf][nf][1]);
            *(float2*)&Cs[(r0+8)*132 + cb] = make_float2(acc[mf][nf][2], acc[mf][nf][3]);
        }
    }
    __syncthreads();

    // ---- fused epilogue ----
    for (int r = wid; r < 128; r += 8) {
        float4 v = *(const float4*)&Cs[r*132 + lane*4];
        size_t go = (size_t)(m0 + r)*CC + lane*4;
        if (p.mode == 0) { *(float4*)&p.out[go] = v; continue; }
        float s  = v.x + v.y + v.z + v.w;
        float sq = v.x*v.x + v.y*v.y + v.z*v.z + v.w*v.w;
        #pragma unroll
        for (int o = 16; o > 0; o >>= 1) {
            s  += __shfl_xor_sync(0xffffffffu, s,  o);
            sq += __shfl_xor_sync(0xffffffffu, sq, o);
        }
        float mu  = s  * (1.0f/CC);
        float var = sq * (1.0f/CC) - mu*mu;
        float sc  = rsqrtf(var + 1e-5f);
        float4 gg = *(const float4*)&p.g[lane*4];
        float4 bv = *(const float4*)&p.b[lane*4];
        float4 y;
        y.x = (v.x - mu)*sc*gg.x + bv.x;
        y.y = (v.y - mu)*sc*gg.y + bv.y;
        y.z = (v.z - mu)*sc*gg.z + bv.z;
        y.w = (v.w - mu)*sc*gg.w + bv.w;
        if (p.mode == 3) {
            float4 rr = *(const float4*)&p.res[go];
            y.x += rr.x; y.y += rr.y; y.z += rr.z; y.w += rr.w;
            y.x = fmaxf(y.x, 0.f); y.y = fmaxf(y.y, 0.f);
            y.z = fmaxf(y.z, 0.f); y.w = fmaxf(y.w, 0.f);
        }
        *(float4*)&p.out[go] = y;
    }
}

// ---------------- small elementwise / row kernels ----------------
__global__ void k_mlp(const float* __restrict__ x, const float* __restrict__ w0,
                      const float* __restrict__ b0, float* __restrict__ out) {
    int idx = blockIdx.x*256 + threadIdx.x;
    int n = idx >> 5, q = (idx & 31) << 2;
    float x0 = x[(size_t)n*2], x1 = x[(size_t)n*2 + 1];
    float4 wa = *(const float4*)&w0[q];
    float4 wb = *(const float4*)&w0[CC + q];
    float4 bb = *(const float4*)&b0[q];
    float4 h;
    h.x = fmaxf(fmaf(x1, wb.x, fmaf(x0, wa.x, bb.x)), 0.f);
    h.y = fmaxf(fmaf(x1, wb.y, fmaf(x0, wa.y, bb.y)), 0.f);
    h.z = fmaxf(fmaf(x1, wb.z, fmaf(x0, wa.z, bb.z)), 0.f);
    h.w = fmaxf(fmaf(x1, wb.w, fmaf(x0, wa.w, bb.w)), 0.f);
    *(float4*)&out[(size_t)n*CC + q] = h;
}

__global__ void k_addrelu(const float* __restrict__ a, const float* __restrict__ b) {
    size_t idx = (size_t)(blockIdx.x*256 + threadIdx.x) * 4;
    float4 u = *(const float4*)&a[idx];
    float4 v = *(const float4*)&b[idx];
    float4 y;
    y.x = fmaxf(u.x + v.x, 0.f); y.y = fmaxf(u.y + v.y, 0.f);
    y.z = fmaxf(u.z + v.z, 0.f); y.w = fmaxf(u.w + v.w, 0.f);
    *(float4*)&g_feat[idx] = y;
}

__global__ void k_gn_relu(const float* __restrict__ g, const float* __restrict__ b) {
    int row = blockIdx.x*8 + (threadIdx.x >> 5);
    int lane = threadIdx.x & 31;
    float4 v = *(const float4*)&g_temp[(size_t)row*CC + lane*4];
    float s  = v.x + v.y + v.z + v.w;
    float sq = v.x*v.x + v.y*v.y + v.z*v.z + v.w*v.w;
    #pragma unroll
    for (int o = 16; o > 0; o >>= 1) {
        s  += __shfl_xor_sync(0xffffffffu, s,  o);
        sq += __shfl_xor_sync(0xffffffffu, sq, o);
    }
    float mu  = s  * (1.0f/CC);
    float var = sq * (1.0f/CC) - mu*mu;
    float sc  = rsqrtf(var + 1e-5f);
    float4 gg = *(const float4*)&g[lane*4];
    float4 bv = *(const float4*)&b[lane*4];
    float4 y;
    y.x = fmaxf((v.x - mu)*sc*gg.x + bv.x, 0.f);
    y.y = fmaxf((v.y - mu)*sc*gg.y + bv.y, 0.f);
    y.z = fmaxf((v.z - mu)*sc*gg.z + bv.z, 0.f);
    y.w = fmaxf((v.w - mu)*sc*gg.w + bv.w, 0.f);
    *(float4*)&g_feat2[(size_t)row*CC + lane*4] = y;
}

__global__ void k_gather(const int* __restrict__ vl) {
    int idx = blockIdx.x*256 + threadIdx.x;
    int e = idx >> 5, q = (idx & 31) << 2;
    int v = vl[e];
    *(float4*)&g_gath[(size_t)e*CC + q] = *(const float4*)&g_feat[(size_t)v*CC + q];
}

__global__ void k_scatter(const int* __restrict__ ul) {
    int idx = blockIdx.x*256 + threadIdx.x;
    int e = idx >> 5, q = (idx & 31) << 2;
    int u = ul[e];
    float4 f = *(const float4*)&g_gout[(size_t)e*CC + q];
    float* d = &g_temp[(size_t)u*CC + q];
    atomicAdd(d + 0, f.x); atomicAdd(d + 1, f.y);
    atomicAdd(d + 2, f.z); atomicAdd(d + 3, f.w);
}

// ---------------- host orchestration ----------------
extern "C" void kernel_launch(void* const* d_in, const int* in_sizes, int n_in,
                              void* d_out, int out_size) {
    const float* ctrs   = (const float*)d_in[0];
    const float* feats  = (const float*)d_in[1];
    const int* pre_u    = (const int*)d_in[2];
    const int* pre_v    = (const int*)d_in[3];
    const int* suc_u    = (const int*)d_in[4];
    const int* suc_v    = (const int*)d_in[5];
    const int* left_u   = (const int*)d_in[6];
    const int* left_v   = (const int*)d_in[7];
    const int* right_u  = (const int*)d_in[8];
    const int* right_v  = (const int*)d_in[9];
    const float* ic_w0  = (const float*)d_in[10];
    const float* ic_b0  = (const float*)d_in[11];
    const float* ic_w1  = (const float*)d_in[12];
    const float* ic_g   = (const float*)d_in[13];
    const float* ic_bt  = (const float*)d_in[14];
    const float* if_w0  = (const float*)d_in[15];
    const float* if_b0  = (const float*)d_in[16];
    const float* if_w1  = (const float*)d_in[17];
    const float* if_g   = (const float*)d_in[18];
    const float* if_bt  = (const float*)d_in[19];
    const float* ctr_w  = (const float*)d_in[20];
    const float* pre_w  = (const float*)d_in[21];
    const float* suc_w  = (const float*)d_in[22];
    const float* left_w = (const float*)d_in[23];
    const float* right_w= (const float*)d_in[24];
    const float* norm_g = (const float*)d_in[25];
    const float* norm_b = (const float*)d_in[26];
    const float* ctr2_w = (const float*)d_in[27];
    const float* ctr2_g = (const float*)d_in[28];
    const float* ctr2_b = (const float*)d_in[29];

    void* q;
    float *fp, *f2p, *tp, *ap, *gp, *gop; void* cntp;
    cudaGetSymbolAddress(&q, g_feat);  fp  = (float*)q;
    cudaGetSymbolAddress(&q, g_feat2); f2p = (float*)q;
    cudaGetSymbolAddress(&q, g_temp);  tp  = (float*)q;
    cudaGetSymbolAddress(&q, g_agg);   ap  = (float*)q;
    cudaGetSymbolAddress(&q, g_gath);  gp  = (float*)q;
    cudaGetSymbolAddress(&q, g_gout);  gop = (float*)q;
    cudaGetSymbolAddress(&cntp, g_cnt);

    cudaFuncSetAttribute(k_gemm_tc, cudaFuncAttributeMaxDynamicSharedMemorySize, SMEM_TC);

    // ---- weight prep + CSR build ----
    k_wprep<<<NSLOT, 256>>>(ic_w1, if_w1, ctr_w, pre_w, suc_w, left_w, right_w, ctr2_w);
    cudaMemsetAsync(cntp, 0, sizeof(int)*NLIST*NN, 0);
    k_count<<<NLIST*EE/256, 256>>>(pre_u, suc_u);
    k_scanA<<<dim3(GSEG, NLIST), 256>>>();
    k_scanB<<<NLIST, GSEG>>>();
    k_scanC<<<dim3(GSEG, NLIST), 256>>>();
    k_fill<<<NLIST*EE/256, 256>>>(pre_u, pre_v, suc_u, suc_v);

    // ---- input MLPs ----
    k_mlp<<<NN*32/256, 256>>>(ctrs,  ic_w0, ic_b0, tp);
    k_mlp<<<NN*32/256, 256>>>(feats, if_w0, if_b0, f2p);
    {
        GemmP p = {};
        p.A[0] = tp; p.slot[0] = 0; p.nch = 1; p.mode = 1;
        p.g = ic_g; p.b = ic_bt; p.out = ap;
        k_gemm_tc<<<NN/128, 256, SMEM_TC>>>(p);
        p.A[0] = f2p; p.slot[0] = 1; p.g = if_g; p.b = if_bt;
        p.out = ap + (size_t)NN*CC;
        k_gemm_tc<<<NN/128, 256, SMEM_TC>>>(p);
    }
    k_addrelu<<<NN*32/256, 256>>>(ap, ap + (size_t)NN*CC);

    // ---- 6 fusion blocks ----
    for (int i = 0; i < BB; i++) {
        int base = 2 + i*16;
        k_aggregate<<<dim3(NN/8, NLIST), 256>>>();

        GemmP pb = {};
        pb.A[0] = fp; pb.slot[0] = base + 0;
        for (int s = 0; s < SS; s++) {
            pb.A[1+s] = ap + (size_t)s*NN*CC;        pb.slot[1+s] = base + 1 + s;
            pb.A[7+s] = ap + (size_t)(SS + s)*NN*CC; pb.slot[7+s] = base + 7 + s;
        }
        pb.nch = 13; pb.mode = 0; pb.out = tp;
        k_gemm_tc<<<NN/128, 256, SMEM_TC>>>(pb);

        {
            GemmP ps = {};
            ps.nch = 1; ps.mode = 0; ps.A[0] = gp; ps.out = gop;
            k_gather<<<ELL*32/256, 256>>>(left_v);
            ps.slot[0] = base + 13;
            k_gemm_tc<<<ELL/128, 256, SMEM_TC>>>(ps);
            k_scatter<<<ELL*32/256, 256>>>(left_u);
            k_gather<<<ELL*32/256, 256>>>(right_v);
            ps.slot[0] = base + 14;
            k_gemm_tc<<<ELL/128, 256, SMEM_TC>>>(ps);
            k_scatter<<<ELL*32/256, 256>>>(right_u);
        }

        k_gn_relu<<<NN/8, 256>>>(norm_g + (size_t)i*CC, norm_b + (size_t)i*CC);

        {
            GemmP p2 = {};
            p2.A[0] = f2p; p2.slot[0] = base + 15;
            p2.nch = 1; p2.mode = 3;
            p2.g = ctr2_g + (size_t)i*CC; p2.b = ctr2_b + (size_t)i*CC;
            p2.res = fp;
            p2.out = (i == BB-1) ? (float*)d_out : fp;
            k_gemm_tc<<<NN/128, 256, SMEM_TC>>>(p2);
        }
    }
}